// round 5
// baseline (speedup 1.0000x reference)
#include <cuda_runtime.h>
#include <cstdint>
#include <math.h>

// ---------------- problem constants ----------------
#define BATCH   64
#define NPATCH  196
#define NVIS    49
#define ENC     768
#define DEC     512
#define FFN     2048
#define OUTD    3072      // 16*16*12
#define NLAYERS 8
#define NHEADS  16
#define HD      32
#define IMG     224
#define CIN     12
#define PS      16

#define TOK_FULL (BATCH*NPATCH)   // 12544
#define TOK_VIS  (BATCH*NVIS)     // 3136

// rounded-weight scratch offsets (floats)
#define OFF_WP   0
#define OFF_WE2D (OFF_WP   + OUTD*ENC)                 // 2359296
#define OFF_WQKV (OFF_WE2D + ENC*DEC)                  // +393216
#define OFF_WO   (OFF_WQKV + NLAYERS*DEC*3*DEC)        // +6291456
#define OFF_W1   (OFF_WO   + NLAYERS*DEC*DEC)          // +2097152
#define OFF_W2   (OFF_W1   + NLAYERS*DEC*FFN)          // +8388608
#define OFF_WR   (OFF_W2   + NLAYERS*FFN*DEC)          // +8388608
#define WTS_TOTAL (OFF_WR  + DEC*OUTD)                 // 29491200

// ---------------- scratch (device globals; no allocation) ----------------
__device__ float g_vp  [TOK_VIS * OUTD];
__device__ float g_enc [TOK_VIS * ENC];
__device__ float g_dec [TOK_VIS * DEC];
__device__ float g_h   [TOK_FULL * DEC];
__device__ float g_qkv [TOK_FULL * 3*DEC];
__device__ float g_attn[TOK_FULL * DEC];
__device__ float g_ffn [TOK_FULL * FFN];
__device__ float g_tmp [TOK_FULL * DEC];
__device__ float g_wts [WTS_TOTAL];
__device__ int   g_vis_idx[TOK_VIS];
__device__ int   g_slot[TOK_FULL];
__device__ int   g_mode;

// ---------------- mask dtype detection ----------------
__global__ void detect_mask_mode(const void* mask) {
    if (threadIdx.x != 0 || blockIdx.x != 0) return;
    {
        const int* p = (const int*)mask;
        bool ok = true; int s = 0;
        for (int i = 0; i < NPATCH; i++) { int v = p[i]; if (v != 0 && v != 1) { ok = false; break; } s += v; }
        if (ok && s == NPATCH - NVIS) { g_mode = 0; return; }
    }
    {
        const unsigned char* p = (const unsigned char*)mask;
        int s = 0;
        for (int i = 0; i < NPATCH; i++) s += (p[i] != 0);
        if (s == NPATCH - NVIS) { g_mode = 1; return; }
    }
    g_mode = 2;
}

__global__ void build_indices(const void* mask) {
    int b = blockIdx.x;
    if (threadIdx.x != 0) return;
    int mode = g_mode;
    const int*           pi = (const int*)mask;
    const unsigned char* pb = (const unsigned char*)mask;
    const float*         pf = (const float*)mask;
    int cnt = 0;
    for (int n = 0; n < NPATCH; n++) {
        int idx = b * NPATCH + n;
        bool m;
        if (mode == 0)      m = (pi[idx] != 0);
        else if (mode == 1) m = (pb[idx] != 0);
        else                m = (pf[idx] != 0.0f);
        if (!m) {
            if (cnt < NVIS) g_vis_idx[b * NVIS + cnt] = n;
            g_slot[idx] = cnt;
            cnt++;
        } else {
            g_slot[idx] = -1;
        }
    }
}

// ---------------- gather visible patches ----------------
__global__ void gather_patches(const float* __restrict__ x) {
    int idx = blockIdx.x * blockDim.x + threadIdx.x;
    if (idx >= TOK_VIS * OUTD) return;
    int f  = idx % OUTD;
    int bv = idx / OUTD;
    int b  = bv / NVIS;
    int n  = g_vis_idx[bv];
    int c  = f >> 8;
    int r  = f & 255;
    int ph = r >> 4, pw = r & 15;
    int hp = n / 14, wp = n % 14;
    g_vp[idx] = x[(((size_t)(b * CIN + c)) * IMG + hp * PS + ph) * IMG + wp * PS + pw];
}

// ---------------- tf32 helpers ----------------
__device__ __forceinline__ void cp_async16(uint32_t dst, const void* src, int srcBytes) {
    asm volatile("cp.async.ca.shared.global [%0], [%1], 16, %2;\n"
                 :: "r"(dst), "l"(src), "r"(srcBytes));
}
__device__ __forceinline__ void cp_commit() {
    asm volatile("cp.async.commit_group;\n");
}
template<int N_>
__device__ __forceinline__ void cp_wait() {
    asm volatile("cp.async.wait_group %0;\n" :: "n"(N_));
}
__device__ __forceinline__ uint32_t f2tf32(float v) {
    uint32_t r;
    asm("cvt.rna.tf32.f32 %0, %1;\n" : "=r"(r) : "f"(v));
    return r;
}
__device__ __forceinline__ void mma_tf32(float c[4], const uint32_t a[4], const uint32_t b[2]) {
    asm volatile(
        "mma.sync.aligned.m16n8k8.row.col.f32.tf32.tf32.f32 "
        "{%0,%1,%2,%3}, {%4,%5,%6,%7}, {%8,%9}, {%0,%1,%2,%3};\n"
        : "+f"(c[0]), "+f"(c[1]), "+f"(c[2]), "+f"(c[3])
        : "r"(a[0]), "r"(a[1]), "r"(a[2]), "r"(a[3]), "r"(b[0]), "r"(b[1]));
}

// ---------------- weight pre-rounding (fp32 -> tf32-rounded fp32 bits) ------
__global__ void round_weights(const float* __restrict__ src, float* __restrict__ dst, int n4) {
    int i = blockIdx.x * blockDim.x + threadIdx.x;
    if (i >= n4) return;
    float4 v = ((const float4*)src)[i];
    uint4 o;
    o.x = f2tf32(v.x); o.y = f2tf32(v.y); o.z = f2tf32(v.z); o.w = f2tf32(v.w);
    ((uint4*)dst)[i] = o;
}

// =====================================================================
// tf32 mma.sync GEMM: C[M,N] = A[M,K] @ Br[K,N] (+bias) (+gelu | +residual)
// Br must be PRE-ROUNDED to tf32 bits. A is cvt.rna'd from fragments.
// 128x128 block, BK=16, 512 threads (16 warps 4x4), warp tile 32x32.
// 3-stage cp.async pipeline, one __syncthreads per K-iteration.
// Requires N % 128 == 0, K % 16 == 0. M guarded.
// =====================================================================
#define BM 128
#define BN 128
#define BKT 16
#define AST 20      // A smem row stride (floats): 16 + 4 pad
#define BST 136     // B smem row stride (floats): 128 + 8 pad
#define STAGES 3
#define A_STAGE (BM * AST)
#define B_STAGE (BKT * BST)
#define GEMM_SMEM_BYTES (STAGES * (A_STAGE + B_STAGE) * 4)   // 56832

template<int EPI>  // 0=bias 1=bias+gelu 2=bias+residual
__global__ __launch_bounds__(512)
void gemm_mma(const float* __restrict__ A, const float* __restrict__ B,
              const float* __restrict__ bias, const float* __restrict__ R,
              float* __restrict__ C, int M, int N, int K)
{
    extern __shared__ float dsm[];
    float* As = dsm;                          // [STAGES][A_STAGE]
    float* Bs = dsm + STAGES * A_STAGE;       // [STAGES][B_STAGE]

    const int tid  = threadIdx.x;
    const int wid  = tid >> 5;
    const int lane = tid & 31;
    const int g    = lane >> 2;    // groupID 0..7
    const int tig  = lane & 3;     // thread in group 0..3
    const int wm   = wid & 3;      // warp row (4)
    const int wn   = wid >> 2;     // warp col (4)
    const int rowBase = blockIdx.y * BM;
    const int colBase = blockIdx.x * BN;

    float acc[2][4][4];
    #pragma unroll
    for (int mt = 0; mt < 2; mt++)
        #pragma unroll
        for (int nt = 0; nt < 4; nt++)
            #pragma unroll
            for (int r = 0; r < 4; r++) acc[mt][nt][r] = 0.f;

    const uint32_t sA = (uint32_t)__cvta_generic_to_shared(As);
    const uint32_t sB = (uint32_t)__cvta_generic_to_shared(Bs);

    // loader indices: 512 threads, 1 float4 each for A (128x16) and B (16x128)
    const int aR = tid >> 2, aC = tid & 3;
    const int bR = tid >> 5, bC = tid & 31;

    const int nIters = K / BKT;

    // ---- prologue: stages 0 and 1 ----
    #pragma unroll
    for (int pre = 0; pre < 2; pre++) {
        if (pre < nIters) {
            const int k0 = pre * BKT;
            {
                int gRow = rowBase + aR;
                int srcB = (gRow < M) ? 16 : 0;
                int gClamp = (gRow < M) ? gRow : 0;
                cp_async16(sA + (uint32_t)((pre * A_STAGE + aR * AST + aC * 4) * 4),
                           A + (size_t)gClamp * K + k0 + aC * 4, srcB);
            }
            cp_async16(sB + (uint32_t)((pre * B_STAGE + bR * BST + bC * 4) * 4),
                       B + (size_t)(k0 + bR) * N + colBase + bC * 4, 16);
        }
        cp_commit();
    }

    int stg = 0, lstg = 2;
    for (int it = 0; it < nIters; it++) {
        if (it + 1 < nIters) cp_wait<1>(); else cp_wait<0>();
        __syncthreads();

        if (it + 2 < nIters) {
            const int k0 = (it + 2) * BKT;
            {
                int gRow = rowBase + aR;
                int srcB = (gRow < M) ? 16 : 0;
                int gClamp = (gRow < M) ? gRow : 0;
                cp_async16(sA + (uint32_t)((lstg * A_STAGE + aR * AST + aC * 4) * 4),
                           A + (size_t)gClamp * K + k0 + aC * 4, srcB);
            }
            cp_async16(sB + (uint32_t)((lstg * B_STAGE + bR * BST + bC * 4) * 4),
                       B + (size_t)(k0 + bR) * N + colBase + bC * 4, 16);
        }
        cp_commit();

        const float* Asl = As + stg * A_STAGE;
        const float* Bsl = Bs + stg * B_STAGE;
        #pragma unroll
        for (int ks = 0; ks < 2; ks++) {
            // B fragments: already tf32 bits, straight bit-load
            uint32_t bfrag[4][2];
            #pragma unroll
            for (int nt = 0; nt < 4; nt++) {
                int ncol = wn * 32 + nt * 8 + g;
                bfrag[nt][0] = __float_as_uint(Bsl[(ks * 8 + tig)     * BST + ncol]);
                bfrag[nt][1] = __float_as_uint(Bsl[(ks * 8 + tig + 4) * BST + ncol]);
            }
            // A fragments: cvt.rna to tf32
            uint32_t afrag[2][4];
            #pragma unroll
            for (int mt = 0; mt < 2; mt++) {
                int r0 = wm * 32 + mt * 16 + g;
                afrag[mt][0] = f2tf32(Asl[(r0)     * AST + ks * 8 + tig]);
                afrag[mt][1] = f2tf32(Asl[(r0 + 8) * AST + ks * 8 + tig]);
                afrag[mt][2] = f2tf32(Asl[(r0)     * AST + ks * 8 + tig + 4]);
                afrag[mt][3] = f2tf32(Asl[(r0 + 8) * AST + ks * 8 + tig + 4]);
            }
            #pragma unroll
            for (int mt = 0; mt < 2; mt++)
                #pragma unroll
                for (int nt = 0; nt < 4; nt++)
                    mma_tf32(acc[mt][nt], afrag[mt], bfrag[nt]);
        }

        stg = (stg + 1 == STAGES) ? 0 : stg + 1;
        lstg = (lstg + 1 == STAGES) ? 0 : lstg + 1;
    }

    // ---- epilogue: fused bias / gelu / residual, float2 stores ----
    #pragma unroll
    for (int mt = 0; mt < 2; mt++) {
        int row0 = rowBase + wm * 32 + mt * 16 + g;
        #pragma unroll
        for (int nt = 0; nt < 4; nt++) {
            int col = colBase + wn * 32 + nt * 8 + tig * 2;
            float b0 = bias[col], b1 = bias[col + 1];
            #pragma unroll
            for (int half = 0; half < 2; half++) {
                int row = row0 + half * 8;
                if (row >= M) continue;
                float v0 = acc[mt][nt][half * 2 + 0] + b0;
                float v1 = acc[mt][nt][half * 2 + 1] + b1;
                if (EPI == 1) {
                    v0 = 0.5f * v0 * (1.0f + erff(v0 * 0.70710678118654752f));
                    v1 = 0.5f * v1 * (1.0f + erff(v1 * 0.70710678118654752f));
                }
                if (EPI == 2) {
                    float2 rv = *(const float2*)(R + (size_t)row * N + col);
                    v0 += rv.x; v1 += rv.y;
                }
                float2 o; o.x = v0; o.y = v1;
                *(float2*)(C + (size_t)row * N + col) = o;
            }
        }
    }
}

// ---------------- mask-token assembly + pos embed ----------------
__global__ void assemble(const float* __restrict__ mask_token,
                         const float* __restrict__ pos) {
    int idx = blockIdx.x * blockDim.x + threadIdx.x;
    if (idx >= TOK_FULL * DEC) return;
    int d  = idx & (DEC - 1);
    int bn = idx >> 9;
    int n  = bn % NPATCH;
    int b  = bn / NPATCH;
    int sl = g_slot[bn];
    float v = (sl < 0) ? mask_token[d] : g_dec[(size_t)(b * NVIS + sl) * DEC + d];
    g_h[idx] = v + pos[n * DEC + d];
}

// ---------------- attention, one block per (b, head) ----------
// Scores are tiny (|d| <~ 1), so softmax runs without max-subtraction:
// s = sum(exp d), o = sum(exp d * V). Mathematically identical.
__global__ __launch_bounds__(224)
void attn_kernel(const float* __restrict__ qkv, float* __restrict__ out) {
    const int S = NPATCH;
    int b = blockIdx.x >> 4;
    int h = blockIdx.x & 15;
    int tid = threadIdx.x;
    __shared__ float Kt[64][HD];
    __shared__ float Vt[64][HD];

    float q[HD];
    const float* qbase = qkv + (size_t)(b * S) * (3 * DEC) + h * HD;
    if (tid < S) {
        const float* qp = qbase + (size_t)tid * (3 * DEC);
        #pragma unroll
        for (int k = 0; k < HD; k++) q[k] = qp[k];
    }
    float o[HD];
    #pragma unroll
    for (int k = 0; k < HD; k++) o[k] = 0.f;
    float s = 0.f;
    const float scale = 0.17677669529663689f;

    for (int j0 = 0; j0 < S; j0 += 64) {
        int jn = min(64, S - j0);
        for (int idx = tid; idx < jn * HD; idx += blockDim.x) {
            int jj = idx >> 5, kk = idx & 31;
            const float* base = qkv + (size_t)(b * S + j0 + jj) * (3 * DEC) + h * HD;
            Kt[jj][kk] = base[DEC + kk];
            Vt[jj][kk] = base[2 * DEC + kk];
        }
        __syncthreads();
        if (tid < S) {
            #pragma unroll 2
            for (int jj = 0; jj < jn; jj++) {
                float d0 = 0.f, d1 = 0.f, d2 = 0.f, d3 = 0.f;
                #pragma unroll
                for (int k = 0; k < HD; k += 4) {
                    d0 = fmaf(q[k],     Kt[jj][k],     d0);
                    d1 = fmaf(q[k + 1], Kt[jj][k + 1], d1);
                    d2 = fmaf(q[k + 2], Kt[jj][k + 2], d2);
                    d3 = fmaf(q[k + 3], Kt[jj][k + 3], d3);
                }
                float d = ((d0 + d1) + (d2 + d3)) * scale;
                float p = __expf(d);
                s += p;
                #pragma unroll
                for (int k = 0; k < HD; k++) o[k] = fmaf(p, Vt[jj][k], o[k]);
            }
        }
        __syncthreads();
    }
    if (tid < S) {
        float inv = 1.f / s;
        float* op = out + (size_t)(b * S + tid) * DEC + h * HD;
        #pragma unroll
        for (int k = 0; k < HD; k++) op[k] = o[k] * inv;
    }
}

// ---------------- layernorm over last dim 512 ----------------
__global__ __launch_bounds__(128)
void ln_kernel(const float* __restrict__ X, const float* __restrict__ g,
               const float* __restrict__ bta, float* __restrict__ Y) {
    int row = blockIdx.x;
    int tid = threadIdx.x;
    const float* x = X + (size_t)row * DEC;
    float v[4];
    float sum = 0.f, sq = 0.f;
    #pragma unroll
    for (int i = 0; i < 4; i++) {
        v[i] = x[tid + i * 128];
        sum += v[i];
        sq  += v[i] * v[i];
    }
    #pragma unroll
    for (int o = 16; o > 0; o >>= 1) {
        sum += __shfl_xor_sync(0xffffffffu, sum, o);
        sq  += __shfl_xor_sync(0xffffffffu, sq,  o);
    }
    __shared__ float s1[4], s2[4];
    int w = tid >> 5;
    if ((tid & 31) == 0) { s1[w] = sum; s2[w] = sq; }
    __syncthreads();
    float tot  = s1[0] + s1[1] + s1[2] + s1[3];
    float tot2 = s2[0] + s2[1] + s2[2] + s2[3];
    float mean = tot * (1.f / DEC);
    float var  = tot2 * (1.f / DEC) - mean * mean;
    float r = rsqrtf(var + 1e-5f);
    float* y = Y + (size_t)row * DEC;
    #pragma unroll
    for (int i = 0; i < 4; i++) {
        int c = tid + i * 128;
        y[c] = (v[i] - mean) * r * g[c] + bta[c];
    }
}

// ---------------- host orchestration ----------------
static void launch_gemm(int epi, const float* A, const float* B, const float* bias,
                        const float* R, float* C, int M, int N, int K) {
    dim3 grid(N / 128, (M + 127) / 128);
    if (epi == 0)      gemm_mma<0><<<grid, 512, GEMM_SMEM_BYTES>>>(A, B, bias, R, C, M, N, K);
    else if (epi == 1) gemm_mma<1><<<grid, 512, GEMM_SMEM_BYTES>>>(A, B, bias, R, C, M, N, K);
    else               gemm_mma<2><<<grid, 512, GEMM_SMEM_BYTES>>>(A, B, bias, R, C, M, N, K);
}

static void launch_round(const float* src, float* dst, long long n) {
    int n4 = (int)(n / 4);
    round_weights<<<(n4 + 255) / 256, 256>>>(src, dst, n4);
}

extern "C" void kernel_launch(void* const* d_in, const int* in_sizes, int n_in,
                              void* d_out, int out_size) {
    const float* x          = (const float*)d_in[0];
    const void*  mask       = d_in[1];
    const float* Wp         = (const float*)d_in[3];
    const float* bp         = (const float*)d_in[4];
    const float* We2d       = (const float*)d_in[5];
    const float* be2d       = (const float*)d_in[6];
    const float* mask_token = (const float*)d_in[7];
    const float* pos        = (const float*)d_in[8];
    const float* Wqkv       = (const float*)d_in[9];
    const float* bqkv       = (const float*)d_in[10];
    const float* Wo         = (const float*)d_in[11];
    const float* bo         = (const float*)d_in[12];
    const float* ln1g       = (const float*)d_in[13];
    const float* ln1b       = (const float*)d_in[14];
    const float* W1         = (const float*)d_in[15];
    const float* b1         = (const float*)d_in[16];
    const float* W2         = (const float*)d_in[17];
    const float* b2         = (const float*)d_in[18];
    const float* ln2g       = (const float*)d_in[19];
    const float* ln2b       = (const float*)d_in[20];
    const float* Wr         = (const float*)d_in[21];
    const float* br         = (const float*)d_in[22];
    float* out = (float*)d_out;

    static bool attrs_set = false;
    if (!attrs_set) {
        cudaFuncSetAttribute(gemm_mma<0>, cudaFuncAttributeMaxDynamicSharedMemorySize, GEMM_SMEM_BYTES);
        cudaFuncSetAttribute(gemm_mma<1>, cudaFuncAttributeMaxDynamicSharedMemorySize, GEMM_SMEM_BYTES);
        cudaFuncSetAttribute(gemm_mma<2>, cudaFuncAttributeMaxDynamicSharedMemorySize, GEMM_SMEM_BYTES);
        attrs_set = true;
    }

    float *p_vp, *p_enc, *p_dec, *p_h, *p_qkv, *p_attn, *p_ffn, *p_tmp, *p_wts;
    cudaGetSymbolAddress((void**)&p_vp,  g_vp);
    cudaGetSymbolAddress((void**)&p_enc, g_enc);
    cudaGetSymbolAddress((void**)&p_dec, g_dec);
    cudaGetSymbolAddress((void**)&p_h,   g_h);
    cudaGetSymbolAddress((void**)&p_qkv, g_qkv);
    cudaGetSymbolAddress((void**)&p_attn,g_attn);
    cudaGetSymbolAddress((void**)&p_ffn, g_ffn);
    cudaGetSymbolAddress((void**)&p_tmp, g_tmp);
    cudaGetSymbolAddress((void**)&p_wts, g_wts);

    // pre-round all weights to tf32 bits (deterministic; runs every call)
    launch_round(Wp,   p_wts + OFF_WP,   (long long)OUTD * ENC);
    launch_round(We2d, p_wts + OFF_WE2D, (long long)ENC * DEC);
    launch_round(Wqkv, p_wts + OFF_WQKV, (long long)NLAYERS * DEC * 3 * DEC);
    launch_round(Wo,   p_wts + OFF_WO,   (long long)NLAYERS * DEC * DEC);
    launch_round(W1,   p_wts + OFF_W1,   (long long)NLAYERS * DEC * FFN);
    launch_round(W2,   p_wts + OFF_W2,   (long long)NLAYERS * FFN * DEC);
    launch_round(Wr,   p_wts + OFF_WR,   (long long)DEC * OUTD);

    detect_mask_mode<<<1, 32>>>(mask);
    build_indices<<<BATCH, 32>>>(mask);

    {
        int total = TOK_VIS * OUTD;
        gather_patches<<<(total + 255) / 256, 256>>>(x);
    }

    // encoder projection: [3136,3072] @ [3072,768]
    launch_gemm(0, p_vp, p_wts + OFF_WP, bp, nullptr, p_enc, TOK_VIS, ENC, OUTD);
    // enc -> dec: [3136,768] @ [768,512]
    launch_gemm(0, p_enc, p_wts + OFF_WE2D, be2d, nullptr, p_dec, TOK_VIS, DEC, ENC);

    {
        int total = TOK_FULL * DEC;
        assemble<<<(total + 255) / 256, 256>>>(mask_token, pos);
    }

    for (int l = 0; l < NLAYERS; l++) {
        const float* Wqkv_l = p_wts + OFF_WQKV + (size_t)l * DEC * 3 * DEC;
        const float* bqkv_l = bqkv + (size_t)l * 3 * DEC;
        const float* Wo_l   = p_wts + OFF_WO + (size_t)l * DEC * DEC;
        const float* bo_l   = bo   + (size_t)l * DEC;
        const float* W1_l   = p_wts + OFF_W1 + (size_t)l * DEC * FFN;
        const float* b1_l   = b1   + (size_t)l * FFN;
        const float* W2_l   = p_wts + OFF_W2 + (size_t)l * FFN * DEC;
        const float* b2_l   = b2   + (size_t)l * DEC;

        launch_gemm(0, p_h, Wqkv_l, bqkv_l, nullptr, p_qkv, TOK_FULL, 3 * DEC, DEC);
        attn_kernel<<<BATCH * NHEADS, 224>>>(p_qkv, p_attn);
        launch_gemm(2, p_attn, Wo_l, bo_l, p_h, p_tmp, TOK_FULL, DEC, DEC);
        ln_kernel<<<TOK_FULL, 128>>>(p_tmp, ln1g + (size_t)l * DEC, ln1b + (size_t)l * DEC, p_h);

        launch_gemm(1, p_h, W1_l, b1_l, nullptr, p_ffn, TOK_FULL, FFN, DEC);
        launch_gemm(2, p_ffn, W2_l, b2_l, p_h, p_tmp, TOK_FULL, DEC, FFN);
        ln_kernel<<<TOK_FULL, 128>>>(p_tmp, ln2g + (size_t)l * DEC, ln2b + (size_t)l * DEC, p_h);
    }

    // reconstruction: [12544,512] @ [512,3072]
    launch_gemm(0, p_h, p_wts + OFF_WR, br, nullptr, out, TOK_FULL, OUTD, DEC);

    const long long recon_elems = (long long)TOK_FULL * OUTD;
    const long long enc_elems   = (long long)TOK_VIS * ENC;
    if ((long long)out_size >= recon_elems + enc_elems) {
        cudaMemcpyAsync(out + recon_elems, p_enc, enc_elems * sizeof(float),
                        cudaMemcpyDeviceToDevice, 0);
    }
}

// round 6
// speedup vs baseline: 1.1932x; 1.1932x over previous
#include <cuda_runtime.h>
#include <cstdint>
#include <math.h>

// ---------------- problem constants ----------------
#define BATCH   64
#define NPATCH  196
#define NVIS    49
#define ENC     768
#define DEC     512
#define FFN     2048
#define OUTD    3072      // 16*16*12
#define NLAYERS 8
#define NHEADS  16
#define HD      32
#define IMG     224
#define CIN     12
#define PS      16

#define TOK_FULL (BATCH*NPATCH)   // 12544
#define TOK_VIS  (BATCH*NVIS)     // 3136

// ---------------- scratch (device globals; no allocation) ----------------
__device__ float g_vp  [TOK_VIS * OUTD];
__device__ float g_enc [TOK_VIS * ENC];
__device__ float g_dec [TOK_VIS * DEC];
__device__ float g_h   [TOK_FULL * DEC];
__device__ float g_qkv [TOK_FULL * 3*DEC];
__device__ float g_attn[TOK_FULL * DEC];
__device__ float g_ffn [TOK_FULL * FFN];
__device__ float g_tmp [TOK_FULL * DEC];
__device__ int   g_vis_idx[TOK_VIS];
__device__ int   g_slot[TOK_FULL];
__device__ int   g_mode;

// ---------------- mask dtype detection ----------------
__global__ void detect_mask_mode(const void* mask) {
    if (threadIdx.x != 0 || blockIdx.x != 0) return;
    {
        const int* p = (const int*)mask;
        bool ok = true; int s = 0;
        for (int i = 0; i < NPATCH; i++) { int v = p[i]; if (v != 0 && v != 1) { ok = false; break; } s += v; }
        if (ok && s == NPATCH - NVIS) { g_mode = 0; return; }
    }
    {
        const unsigned char* p = (const unsigned char*)mask;
        int s = 0;
        for (int i = 0; i < NPATCH; i++) s += (p[i] != 0);
        if (s == NPATCH - NVIS) { g_mode = 1; return; }
    }
    g_mode = 2;
}

__global__ void build_indices(const void* mask) {
    int b = blockIdx.x;
    if (threadIdx.x != 0) return;
    int mode = g_mode;
    const int*           pi = (const int*)mask;
    const unsigned char* pb = (const unsigned char*)mask;
    const float*         pf = (const float*)mask;
    int cnt = 0;
    for (int n = 0; n < NPATCH; n++) {
        int idx = b * NPATCH + n;
        bool m;
        if (mode == 0)      m = (pi[idx] != 0);
        else if (mode == 1) m = (pb[idx] != 0);
        else                m = (pf[idx] != 0.0f);
        if (!m) {
            if (cnt < NVIS) g_vis_idx[b * NVIS + cnt] = n;
            g_slot[idx] = cnt;
            cnt++;
        } else {
            g_slot[idx] = -1;
        }
    }
}

// ---------------- gather visible patches ----------------
__global__ void gather_patches(const float* __restrict__ x) {
    int idx = blockIdx.x * blockDim.x + threadIdx.x;
    if (idx >= TOK_VIS * OUTD) return;
    int f  = idx % OUTD;
    int bv = idx / OUTD;
    int b  = bv / NVIS;
    int n  = g_vis_idx[bv];
    int c  = f >> 8;
    int r  = f & 255;
    int ph = r >> 4, pw = r & 15;
    int hp = n / 14, wp = n % 14;
    g_vp[idx] = x[(((size_t)(b * CIN + c)) * IMG + hp * PS + ph) * IMG + wp * PS + pw];
}

// =====================================================================
// tf32 mma.sync GEMM (R3 winner): C[M,N] = A[M,K] @ B[K,N]
// (+bias) (+gelu | +residual). 128x128 block, BK=16, 256 threads
// (8 warps 2x4), warp tile 64x32, double-buffered cp.async.
// Requires N % 128 == 0, K % 16 == 0. M guarded.
// =====================================================================
#define BM 128
#define BN 128
#define BKT 16
#define AST 20      // A smem row stride (floats): 16 + 4 pad
#define BST 136     // B smem row stride (floats): 128 + 8 pad

__device__ __forceinline__ void cp_async16(uint32_t dst, const void* src, int srcBytes) {
    asm volatile("cp.async.ca.shared.global [%0], [%1], 16, %2;\n"
                 :: "r"(dst), "l"(src), "r"(srcBytes));
}
__device__ __forceinline__ void cp_commit() {
    asm volatile("cp.async.commit_group;\n");
}
template<int N_>
__device__ __forceinline__ void cp_wait() {
    asm volatile("cp.async.wait_group %0;\n" :: "n"(N_));
}
__device__ __forceinline__ uint32_t f2tf32(float v) {
    uint32_t r;
    asm("cvt.rna.tf32.f32 %0, %1;\n" : "=r"(r) : "f"(v));
    return r;
}
__device__ __forceinline__ void mma_tf32(float c[4], const uint32_t a[4], const uint32_t b[2]) {
    asm volatile(
        "mma.sync.aligned.m16n8k8.row.col.f32.tf32.tf32.f32 "
        "{%0,%1,%2,%3}, {%4,%5,%6,%7}, {%8,%9}, {%0,%1,%2,%3};\n"
        : "+f"(c[0]), "+f"(c[1]), "+f"(c[2]), "+f"(c[3])
        : "r"(a[0]), "r"(a[1]), "r"(a[2]), "r"(a[3]), "r"(b[0]), "r"(b[1]));
}

template<int EPI>  // 0=bias 1=bias+gelu 2=bias+residual
__global__ __launch_bounds__(256, 2)
void gemm_mma(const float* __restrict__ A, const float* __restrict__ B,
              const float* __restrict__ bias, const float* __restrict__ R,
              float* __restrict__ C, int M, int N, int K)
{
    __shared__ float As[2][BM * AST];
    __shared__ float Bs[2][BKT * BST];

    const int tid  = threadIdx.x;
    const int wid  = tid >> 5;
    const int lane = tid & 31;
    const int g    = lane >> 2;    // groupID
    const int tig  = lane & 3;     // threadID in group
    const int wm   = wid & 1;      // warp row (2)
    const int wn   = wid >> 1;     // warp col (4)
    const int rowBase = blockIdx.y * BM;
    const int colBase = blockIdx.x * BN;

    float acc[4][4][4];
    #pragma unroll
    for (int mt = 0; mt < 4; mt++)
        #pragma unroll
        for (int nt = 0; nt < 4; nt++)
            #pragma unroll
            for (int r = 0; r < 4; r++) acc[mt][nt][r] = 0.f;

    const uint32_t sA = (uint32_t)__cvta_generic_to_shared(&As[0][0]);
    const uint32_t sB = (uint32_t)__cvta_generic_to_shared(&Bs[0][0]);

    const int aR0 = tid >> 2, aC0 = tid & 3;
    const int bR0 = tid >> 5, bC0 = tid & 31;

    const int nIters = K / BKT;

    // ---- prologue: load tile 0 into buf 0 ----
    {
        const int k0 = 0, buf = 0;
        #pragma unroll
        for (int p = 0; p < 2; p++) {
            int r = aR0 + p * 64, cc = aC0;
            int gRow = rowBase + r;
            int srcB = (gRow < M) ? 16 : 0;
            int gClamp = (gRow < M) ? gRow : 0;
            cp_async16(sA + (uint32_t)((buf * BM * AST + r * AST + cc * 4) * 4),
                       A + (size_t)gClamp * K + k0 + cc * 4, srcB);
        }
        #pragma unroll
        for (int p = 0; p < 2; p++) {
            int r = bR0 + p * 8, cc = bC0;
            cp_async16(sB + (uint32_t)((buf * BKT * BST + r * BST + cc * 4) * 4),
                       B + (size_t)(k0 + r) * N + colBase + cc * 4, 16);
        }
        cp_commit();
    }

    for (int it = 0; it < nIters; it++) {
        const int buf = it & 1;
        if (it + 1 < nIters) {
            const int nbuf = buf ^ 1;
            const int k0 = (it + 1) * BKT;
            #pragma unroll
            for (int p = 0; p < 2; p++) {
                int r = aR0 + p * 64, cc = aC0;
                int gRow = rowBase + r;
                int srcB = (gRow < M) ? 16 : 0;
                int gClamp = (gRow < M) ? gRow : 0;
                cp_async16(sA + (uint32_t)((nbuf * BM * AST + r * AST + cc * 4) * 4),
                           A + (size_t)gClamp * K + k0 + cc * 4, srcB);
            }
            #pragma unroll
            for (int p = 0; p < 2; p++) {
                int r = bR0 + p * 8, cc = bC0;
                cp_async16(sB + (uint32_t)((nbuf * BKT * BST + r * BST + cc * 4) * 4),
                           B + (size_t)(k0 + r) * N + colBase + cc * 4, 16);
            }
            cp_commit();
            cp_wait<1>();
        } else {
            cp_wait<0>();
        }
        __syncthreads();

        // ---- compute on buf ----
        #pragma unroll
        for (int ks = 0; ks < 2; ks++) {
            uint32_t bfrag[4][2];
            #pragma unroll
            for (int nt = 0; nt < 4; nt++) {
                int ncol = wn * 32 + nt * 8 + g;
                bfrag[nt][0] = f2tf32(Bs[buf][(ks * 8 + tig)     * BST + ncol]);
                bfrag[nt][1] = f2tf32(Bs[buf][(ks * 8 + tig + 4) * BST + ncol]);
            }
            uint32_t afrag[4][4];
            #pragma unroll
            for (int mt = 0; mt < 4; mt++) {
                int r0 = wm * 64 + mt * 16 + g;
                afrag[mt][0] = f2tf32(As[buf][(r0)     * AST + ks * 8 + tig]);
                afrag[mt][1] = f2tf32(As[buf][(r0 + 8) * AST + ks * 8 + tig]);
                afrag[mt][2] = f2tf32(As[buf][(r0)     * AST + ks * 8 + tig + 4]);
                afrag[mt][3] = f2tf32(As[buf][(r0 + 8) * AST + ks * 8 + tig + 4]);
            }
            #pragma unroll
            for (int mt = 0; mt < 4; mt++)
                #pragma unroll
                for (int nt = 0; nt < 4; nt++)
                    mma_tf32(acc[mt][nt], afrag[mt], bfrag[nt]);
        }
        __syncthreads();
    }

    // ---- epilogue: fused bias / gelu / residual, float2 stores ----
    #pragma unroll
    for (int mt = 0; mt < 4; mt++) {
        int row0 = rowBase + wm * 64 + mt * 16 + g;
        #pragma unroll
        for (int nt = 0; nt < 4; nt++) {
            int col = colBase + wn * 32 + nt * 8 + tig * 2;
            float b0 = bias[col], b1 = bias[col + 1];
            #pragma unroll
            for (int half = 0; half < 2; half++) {
                int row = row0 + half * 8;
                if (row >= M) continue;
                float v0 = acc[mt][nt][half * 2 + 0] + b0;
                float v1 = acc[mt][nt][half * 2 + 1] + b1;
                if (EPI == 1) {
                    v0 = 0.5f * v0 * (1.0f + erff(v0 * 0.70710678118654752f));
                    v1 = 0.5f * v1 * (1.0f + erff(v1 * 0.70710678118654752f));
                }
                if (EPI == 2) {
                    float2 rv = *(const float2*)(R + (size_t)row * N + col);
                    v0 += rv.x; v1 += rv.y;
                }
                float2 o; o.x = v0; o.y = v1;
                *(float2*)(C + (size_t)row * N + col) = o;
            }
        }
    }
}

// ---------------- mask-token assembly + pos embed ----------------
__global__ void assemble(const float* __restrict__ mask_token,
                         const float* __restrict__ pos) {
    int idx = blockIdx.x * blockDim.x + threadIdx.x;
    if (idx >= TOK_FULL * DEC) return;
    int d  = idx & (DEC - 1);
    int bn = idx >> 9;
    int n  = bn % NPATCH;
    int b  = bn / NPATCH;
    int sl = g_slot[bn];
    float v = (sl < 0) ? mask_token[d] : g_dec[(size_t)(b * NVIS + sl) * DEC + d];
    g_h[idx] = v + pos[n * DEC + d];
}

// ---------------- attention, one block per (b, head), float4 K/V ----------
// Scores are tiny (|d| <~ 1), so softmax runs without max-subtraction:
// s = sum(exp d), o = sum(exp d * V). Mathematically identical to reference.
// K/V staged in smem as float4 rows (128B aligned) -> 16 LDS.128 per key
// instead of 64 scalar LDS (the prior LSU bottleneck).
__global__ __launch_bounds__(224)
void attn_kernel(const float* __restrict__ qkv, float* __restrict__ out) {
    const int S = NPATCH;
    int b = blockIdx.x >> 4;
    int h = blockIdx.x & 15;
    int tid = threadIdx.x;
    __shared__ float4 Kt4[64][8];
    __shared__ float4 Vt4[64][8];

    float4 q4[8];
    const float* qbase = qkv + (size_t)(b * S) * (3 * DEC) + h * HD;
    if (tid < S) {
        const float4* qp = (const float4*)(qbase + (size_t)tid * (3 * DEC));
        #pragma unroll
        for (int i = 0; i < 8; i++) q4[i] = qp[i];
    }
    float4 o4[8];
    #pragma unroll
    for (int i = 0; i < 8; i++) o4[i] = make_float4(0.f, 0.f, 0.f, 0.f);
    float s = 0.f;
    const float scale = 0.17677669529663689f; // 1/sqrt(32)

    for (int j0 = 0; j0 < S; j0 += 64) {
        int jn = min(64, S - j0);
        // stage K/V as float4 (all offsets 128B-aligned)
        for (int idx = tid; idx < jn * 8; idx += blockDim.x) {
            int jj = idx >> 3, kk = idx & 7;
            const float4* base = (const float4*)(qkv + (size_t)(b * S + j0 + jj) * (3 * DEC) + h * HD);
            Kt4[jj][kk] = base[DEC / 4 + kk];
            Vt4[jj][kk] = base[2 * DEC / 4 + kk];
        }
        __syncthreads();
        if (tid < S) {
            for (int jj = 0; jj < jn; jj++) {
                float d0 = 0.f, d1 = 0.f, d2 = 0.f, d3 = 0.f;
                #pragma unroll
                for (int i = 0; i < 8; i++) {
                    float4 kv = Kt4[jj][i];
                    d0 = fmaf(q4[i].x, kv.x, d0);
                    d1 = fmaf(q4[i].y, kv.y, d1);
                    d2 = fmaf(q4[i].z, kv.z, d2);
                    d3 = fmaf(q4[i].w, kv.w, d3);
                }
                float d = ((d0 + d1) + (d2 + d3)) * scale;
                float p = __expf(d);
                s += p;
                #pragma unroll
                for (int i = 0; i < 8; i++) {
                    float4 vv = Vt4[jj][i];
                    o4[i].x = fmaf(p, vv.x, o4[i].x);
                    o4[i].y = fmaf(p, vv.y, o4[i].y);
                    o4[i].z = fmaf(p, vv.z, o4[i].z);
                    o4[i].w = fmaf(p, vv.w, o4[i].w);
                }
            }
        }
        __syncthreads();
    }
    if (tid < S) {
        float inv = 1.f / s;
        float4* op = (float4*)(out + (size_t)(b * S + tid) * DEC + h * HD);
        #pragma unroll
        for (int i = 0; i < 8; i++) {
            float4 v = o4[i];
            v.x *= inv; v.y *= inv; v.z *= inv; v.w *= inv;
            op[i] = v;
        }
    }
}

// ---------------- layernorm over last dim 512 ----------------
__global__ __launch_bounds__(128)
void ln_kernel(const float* __restrict__ X, const float* __restrict__ g,
               const float* __restrict__ bta, float* __restrict__ Y) {
    int row = blockIdx.x;
    int tid = threadIdx.x;
    const float* x = X + (size_t)row * DEC;
    float v[4];
    float sum = 0.f, sq = 0.f;
    #pragma unroll
    for (int i = 0; i < 4; i++) {
        v[i] = x[tid + i * 128];
        sum += v[i];
        sq  += v[i] * v[i];
    }
    #pragma unroll
    for (int o = 16; o > 0; o >>= 1) {
        sum += __shfl_xor_sync(0xffffffffu, sum, o);
        sq  += __shfl_xor_sync(0xffffffffu, sq,  o);
    }
    __shared__ float s1[4], s2[4];
    int w = tid >> 5;
    if ((tid & 31) == 0) { s1[w] = sum; s2[w] = sq; }
    __syncthreads();
    float tot  = s1[0] + s1[1] + s1[2] + s1[3];
    float tot2 = s2[0] + s2[1] + s2[2] + s2[3];
    float mean = tot * (1.f / DEC);
    float var  = tot2 * (1.f / DEC) - mean * mean;
    float r = rsqrtf(var + 1e-5f);
    float* y = Y + (size_t)row * DEC;
    #pragma unroll
    for (int i = 0; i < 4; i++) {
        int c = tid + i * 128;
        y[c] = (v[i] - mean) * r * g[c] + bta[c];
    }
}

// ---------------- host orchestration ----------------
static void launch_gemm(int epi, const float* A, const float* B, const float* bias,
                        const float* R, float* C, int M, int N, int K) {
    dim3 grid(N / 128, (M + 127) / 128);
    if (epi == 0)      gemm_mma<0><<<grid, 256>>>(A, B, bias, R, C, M, N, K);
    else if (epi == 1) gemm_mma<1><<<grid, 256>>>(A, B, bias, R, C, M, N, K);
    else               gemm_mma<2><<<grid, 256>>>(A, B, bias, R, C, M, N, K);
}

extern "C" void kernel_launch(void* const* d_in, const int* in_sizes, int n_in,
                              void* d_out, int out_size) {
    const float* x          = (const float*)d_in[0];
    const void*  mask       = d_in[1];
    const float* Wp         = (const float*)d_in[3];
    const float* bp         = (const float*)d_in[4];
    const float* We2d       = (const float*)d_in[5];
    const float* be2d       = (const float*)d_in[6];
    const float* mask_token = (const float*)d_in[7];
    const float* pos        = (const float*)d_in[8];
    const float* Wqkv       = (const float*)d_in[9];
    const float* bqkv       = (const float*)d_in[10];
    const float* Wo         = (const float*)d_in[11];
    const float* bo         = (const float*)d_in[12];
    const float* ln1g       = (const float*)d_in[13];
    const float* ln1b       = (const float*)d_in[14];
    const float* W1         = (const float*)d_in[15];
    const float* b1         = (const float*)d_in[16];
    const float* W2         = (const float*)d_in[17];
    const float* b2         = (const float*)d_in[18];
    const float* ln2g       = (const float*)d_in[19];
    const float* ln2b       = (const float*)d_in[20];
    const float* Wr         = (const float*)d_in[21];
    const float* br         = (const float*)d_in[22];
    float* out = (float*)d_out;

    float *p_vp, *p_enc, *p_dec, *p_h, *p_qkv, *p_attn, *p_ffn, *p_tmp;
    cudaGetSymbolAddress((void**)&p_vp,  g_vp);
    cudaGetSymbolAddress((void**)&p_enc, g_enc);
    cudaGetSymbolAddress((void**)&p_dec, g_dec);
    cudaGetSymbolAddress((void**)&p_h,   g_h);
    cudaGetSymbolAddress((void**)&p_qkv, g_qkv);
    cudaGetSymbolAddress((void**)&p_attn,g_attn);
    cudaGetSymbolAddress((void**)&p_ffn, g_ffn);
    cudaGetSymbolAddress((void**)&p_tmp, g_tmp);

    detect_mask_mode<<<1, 32>>>(mask);
    build_indices<<<BATCH, 32>>>(mask);

    {
        int total = TOK_VIS * OUTD;
        gather_patches<<<(total + 255) / 256, 256>>>(x);
    }

    // encoder projection: [3136,3072] @ [3072,768]
    launch_gemm(0, p_vp, Wp, bp, nullptr, p_enc, TOK_VIS, ENC, OUTD);
    // enc -> dec: [3136,768] @ [768,512]
    launch_gemm(0, p_enc, We2d, be2d, nullptr, p_dec, TOK_VIS, DEC, ENC);

    {
        int total = TOK_FULL * DEC;
        assemble<<<(total + 255) / 256, 256>>>(mask_token, pos);
    }

    for (int l = 0; l < NLAYERS; l++) {
        const float* Wqkv_l = Wqkv + (size_t)l * DEC * 3 * DEC;
        const float* bqkv_l = bqkv + (size_t)l * 3 * DEC;
        const float* Wo_l   = Wo   + (size_t)l * DEC * DEC;
        const float* bo_l   = bo   + (size_t)l * DEC;
        const float* W1_l   = W1   + (size_t)l * DEC * FFN;
        const float* b1_l   = b1   + (size_t)l * FFN;
        const float* W2_l   = W2   + (size_t)l * FFN * DEC;
        const float* b2_l   = b2   + (size_t)l * DEC;

        launch_gemm(0, p_h, Wqkv_l, bqkv_l, nullptr, p_qkv, TOK_FULL, 3 * DEC, DEC);
        attn_kernel<<<BATCH * NHEADS, 224>>>(p_qkv, p_attn);
        launch_gemm(2, p_attn, Wo_l, bo_l, p_h, p_tmp, TOK_FULL, DEC, DEC);
        ln_kernel<<<TOK_FULL, 128>>>(p_tmp, ln1g + (size_t)l * DEC, ln1b + (size_t)l * DEC, p_h);

        launch_gemm(1, p_h, W1_l, b1_l, nullptr, p_ffn, TOK_FULL, FFN, DEC);
        launch_gemm(2, p_ffn, W2_l, b2_l, p_h, p_tmp, TOK_FULL, DEC, FFN);
        ln_kernel<<<TOK_FULL, 128>>>(p_tmp, ln2g + (size_t)l * DEC, ln2b + (size_t)l * DEC, p_h);
    }

    // reconstruction: [12544,512] @ [512,3072]
    launch_gemm(0, p_h, Wr, br, nullptr, out, TOK_FULL, OUTD, DEC);

    const long long recon_elems = (long long)TOK_FULL * OUTD;
    const long long enc_elems   = (long long)TOK_VIS * ENC;
    if ((long long)out_size >= recon_elems + enc_elems) {
        cudaMemcpyAsync(out + recon_elems, p_enc, enc_elems * sizeof(float),
                        cudaMemcpyDeviceToDevice, 0);
    }
}